// round 2
// baseline (speedup 1.0000x reference)
#include <cuda_runtime.h>

// Triangle_39719857553609:
//   in : decompFE [32768, 2016] float32 (flat strict-lower-triangle, tril(-1) order)
//   out: [32768, 64, 64] float32, symmetric, zero diagonal.
//
// R2: two matrices per CTA, software-pipelined (load B overlaps store A),
// streaming cache hints on both touch-once streams. Pure HBM roofline kernel:
// 264 MB read + 537 MB write.

#define N_ATOMS 64
#define NC2     2016                  // 64*63/2
#define NC2_V4  (NC2 / 4)             // 504
#define MAT     (N_ATOMS * N_ATOMS)   // 4096
#define THREADS 256
#define V4_PER_THREAD (MAT / 4 / THREADS)  // 4

__device__ __forceinline__ float4 ldcs4(const float4* p) {
    return __ldcs(p);
}

__device__ __forceinline__ void load_row(const float4* __restrict__ in4,
                                         float4* __restrict__ s4, int tid)
{
    // 504 float4 loads over 256 threads: iterations tid and tid+256 (partial)
    s4[tid] = ldcs4(in4 + tid);
    if (tid < NC2_V4 - THREADS)
        s4[tid + THREADS] = ldcs4(in4 + tid + THREADS);
}

__device__ __forceinline__ void store_mat(const float* __restrict__ s,
                                          float4* __restrict__ out4, int tid)
{
    #pragma unroll
    for (int q = 0; q < V4_PER_THREAD; q++) {
        const int e4 = tid + q * THREADS;        // float4 index within matrix
        const int i  = e4 >> 4;                  // row (16 float4 per row)
        const int j0 = (e4 & 15) << 2;           // first col of this float4
        const int tri_i = (i * (i - 1)) >> 1;

        float4 v;
        float* vp = reinterpret_cast<float*>(&v);
        #pragma unroll
        for (int m = 0; m < 4; m++) {
            const int j = j0 + m;
            float val;
            if (j < i)       val = s[tri_i + j];                 // lower
            else if (j > i)  val = s[((j * (j - 1)) >> 1) + i];  // mirrored upper
            else             val = 0.0f;                         // diagonal
            vp[m] = val;
        }
        __stcs(out4 + e4, v);   // streaming store: touch-once, evict-first
    }
}

__global__ __launch_bounds__(THREADS) void triangle_kernel(
    const float* __restrict__ in, float* __restrict__ out)
{
    __shared__ float sA[NC2];
    __shared__ float sB[NC2];

    const int tid = threadIdx.x;
    const int b0 = blockIdx.x * 2;        // this CTA handles b0 and b0+1

    const float4* inA = reinterpret_cast<const float4*>(in + (size_t)b0 * NC2);
    const float4* inB = reinterpret_cast<const float4*>(in + (size_t)(b0 + 1) * NC2);
    float4* outA = reinterpret_cast<float4*>(out + (size_t)b0 * MAT);
    float4* outB = reinterpret_cast<float4*>(out + (size_t)(b0 + 1) * MAT);

    // Stage A
    load_row(inA, reinterpret_cast<float4*>(sA), tid);
    __syncthreads();

    // Issue B's loads first (fire-and-forget into sB), then store A.
    // The LDGs for B overlap the STG stream of A.
    load_row(inB, reinterpret_cast<float4*>(sB), tid);
    store_mat(sA, outA, tid);
    __syncthreads();

    // Store B
    store_mat(sB, outB, tid);
}

extern "C" void kernel_launch(void* const* d_in, const int* in_sizes, int n_in,
                              void* d_out, int out_size)
{
    const float* decompFE = (const float*)d_in[0];
    float* out = (float*)d_out;

    const int batch = in_sizes[0] / NC2;   // 32768
    triangle_kernel<<<batch / 2, THREADS>>>(decompFE, out);
}

// round 3
// speedup vs baseline: 1.0196x; 1.0196x over previous
#include <cuda_runtime.h>
#include <cstdint>

// Triangle_39719857553609:
//   in : decompFE [32768, 2016] f32 (flat strict-lower-triangle, tril(-1) order)
//   out: [32768, 64, 64] f32, symmetric, zero diagonal.
//
// R3: bulk-async data movement. One CTA per matrix:
//   cp.async.bulk G->S (8064 B row, mbarrier) -> build 64x64 in smem ->
//   fence.proxy.async -> cp.async.bulk S->G (16 KB matrix, bulk_group).
// Tests whether large contiguous bulk bursts beat per-thread STG streams on
// DRAM scheduling (both hit the same LTS cap per B300_MICROARCH).

#define NC2        2016
#define ROW_BYTES  (NC2 * 4)        // 8064 = 63 * 128, 16B aligned
#define N_ATOMS    64
#define MAT        (N_ATOMS * N_ATOMS)  // 4096
#define MAT_BYTES  (MAT * 4)        // 16384
#define THREADS    256

__device__ __forceinline__ uint32_t smem_u32(const void* p) {
    uint32_t a;
    asm("{ .reg .u64 t; cvta.to.shared.u64 t, %1; cvt.u32.u64 %0, t; }"
        : "=r"(a) : "l"(p));
    return a;
}

__global__ __launch_bounds__(THREADS) void triangle_kernel(
    const float* __restrict__ in, float* __restrict__ out)
{
    __shared__ alignas(16) float s_row[NC2];
    __shared__ alignas(16) float s_mat[MAT];
    __shared__ alignas(8)  uint64_t s_mbar;

    const int tid = threadIdx.x;
    const int b   = blockIdx.x;

    const uint32_t mbar_a = smem_u32(&s_mbar);
    const uint32_t row_a  = smem_u32(s_row);
    const uint32_t mat_a  = smem_u32(s_mat);

    // ---- init mbarrier, then single bulk load of the input row ----
    if (tid == 0)
        asm volatile("mbarrier.init.shared.b64 [%0], 1;" :: "r"(mbar_a) : "memory");
    __syncthreads();

    if (tid == 0) {
        asm volatile("mbarrier.arrive.expect_tx.shared.b64 _, [%0], %1;"
                     :: "r"(mbar_a), "r"((uint32_t)ROW_BYTES) : "memory");
        const float* src = in + (size_t)b * NC2;
        asm volatile(
            "cp.async.bulk.shared::cta.global.mbarrier::complete_tx::bytes "
            "[%0], [%1], %2, [%3];"
            :: "r"(row_a), "l"(src), "r"((uint32_t)ROW_BYTES), "r"(mbar_a)
            : "memory");
    }

    // all threads wait for the row (parity 0)
    asm volatile(
        "{\n\t"
        ".reg .pred p;\n\t"
        "W_%=:\n\t"
        "mbarrier.try_wait.parity.shared.b64 p, [%0], 0;\n\t"
        "@!p bra W_%=;\n\t"
        "}"
        :: "r"(mbar_a) : "memory");

    // ---- build the full symmetric matrix in smem (4 float4 per thread) ----
    float4* m4 = reinterpret_cast<float4*>(s_mat);
    #pragma unroll
    for (int q = 0; q < MAT / 4 / THREADS; q++) {
        const int e4 = tid + q * THREADS;        // float4 index in matrix
        const int i  = e4 >> 4;                  // row (16 float4 per row)
        const int j0 = (e4 & 15) << 2;
        const int tri_i = (i * (i - 1)) >> 1;

        float4 v;
        float* vp = reinterpret_cast<float*>(&v);
        #pragma unroll
        for (int mI = 0; mI < 4; mI++) {
            const int j = j0 + mI;
            float val;
            if (j < i)       val = s_row[tri_i + j];                 // lower
            else if (j > i)  val = s_row[((j * (j - 1)) >> 1) + i];  // upper
            else             val = 0.0f;                             // diag
            vp[mI] = val;
        }
        m4[e4] = v;
    }
    __syncthreads();

    // ---- single 16 KB bulk store to GMEM ----
    if (tid == 0) {
        asm volatile("fence.proxy.async.shared::cta;" ::: "memory");
        float* dst = out + (size_t)b * MAT;
        asm volatile(
            "cp.async.bulk.global.shared::cta.bulk_group [%0], [%1], %2;"
            :: "l"(dst), "r"(mat_a), "r"((uint32_t)MAT_BYTES)
            : "memory");
        asm volatile("cp.async.bulk.commit_group;" ::: "memory");
        asm volatile("cp.async.bulk.wait_group 0;" ::: "memory");
    }
}

extern "C" void kernel_launch(void* const* d_in, const int* in_sizes, int n_in,
                              void* d_out, int out_size)
{
    const float* decompFE = (const float*)d_in[0];
    float* out = (float*)d_out;

    const int batch = in_sizes[0] / NC2;   // 32768
    triangle_kernel<<<batch, THREADS>>>(decompFE, out);
}